// round 2
// baseline (speedup 1.0000x reference)
#include <cuda_runtime.h>
#include <math.h>

#define BB 8
#define LL 1024
#define NT 10
#define SS 2.1972245773362196f   // log(9)

// ---- static device scratch (no allocation allowed) ----
__device__ float g_uu[BB*LL*LL];        // 32 MB
__device__ float g_ah[BB*LL*LL];        // 32 MB
__device__ float g_partial[BB*LL*32];   // per-row partial sums, one slot per col-block
__device__ float g_s[BB*LL];            // s_i = lmbd_i * sigmoid(2*(rowsum_i-1))
__device__ float g_lmbd[BB*LL];

__device__ __forceinline__ float sigm(float v){ return 1.0f/(1.0f+__expf(-v)); }

__device__ __forceinline__ float wsum(float v){
  #pragma unroll
  for (int o=16;o;o>>=1) v += __shfl_xor_sync(0xffffffffu, v, o);
  return v;
}

// m[i,j] from the 4 per-row factors (ba,bu,bc,bg)
__device__ __forceinline__ float mcalc(const float (&fR)[4][32], int r,
                                       const float (&fC)[4][32], int c){
  float bai=fR[0][r], bui=fR[1][r], bci=fR[2][r], bgi=fR[3][r];
  float baj=fC[0][c], buj=fC[1][c], bcj=fC[2][c], bgj=fC[3][c];
  return bai*buj + baj*bui + bci*bgj + bcj*bgi + bui*bgj + buj*bgi;
}

// 3->3(relu)->1(relu) MLP; w layout: [0:9)=W1 (o*3+i), [9:12)=b1, [12:15)=W2, [15]=b2
__device__ __forceinline__ float mlp3(const float* __restrict__ w, float f0, float f1, float f2){
  float h0 = fmaxf(fmaf(w[0],f0,fmaf(w[1],f1,fmaf(w[2],f2,w[9]))),  0.f);
  float h1 = fmaxf(fmaf(w[3],f0,fmaf(w[4],f1,fmaf(w[5],f2,w[10]))), 0.f);
  float h2 = fmaxf(fmaf(w[6],f0,fmaf(w[7],f1,fmaf(w[8],f2,w[11]))), 0.f);
  return fmaxf(fmaf(w[12],h0,fmaf(w[13],h1,fmaf(w[14],h2,w[15]))), 0.f);
}

// triangular pair decode: p = I*(I+1)/2 + J, J <= I
__device__ __forceinline__ void decode_pair(int p, int &I, int &J){
  I = (int)((sqrtf(8.f*(float)p+1.f)-1.f)*0.5f);
  while ((I+1)*(I+2)/2 <= p) ++I;
  while (I*(I+1)/2 > p) --I;
  J = p - I*(I+1)/2;
}

// ---------------- init: uu, a_hat, rowsum partials of a0 ----------------
__global__ void __launch_bounds__(256)
init_kernel(const float* __restrict__ u, const float* __restrict__ x)
{
  int b = blockIdx.y;
  int I, J; decode_pair(blockIdx.x, I, J);
  bool diag = (I==J);
  int i0 = I*32, j0 = J*32;
  int tid = threadIdx.x, tx = tid&31, ty = tid>>5;

  __shared__ float sq1[32][33], sq2[32][33];
  __shared__ float fI[4][32], fJ[4][32];

  if (tid < 32) {
    float4 v = ((const float4*)x)[b*LL + i0 + tid];
    fI[0][tid]=v.x; fI[1][tid]=v.y; fI[2][tid]=v.z; fI[3][tid]=v.w;
  } else if (tid < 64) {
    int l = tid-32;
    float4 v = ((const float4*)x)[b*LL + j0 + l];
    fJ[0][l]=v.x; fJ[1][l]=v.y; fJ[2][l]=v.z; fJ[3][l]=v.w;
  }

  const size_t base = (size_t)b*LL*LL;
  #pragma unroll
  for (int k=0;k<4;k++){
    int r = ty + 8*k;
    size_t g1 = base + (size_t)(i0+r)*LL + j0 + tx;
    float uv = u[g1];
    float uu = sigm(2.f*(uv - SS))*uv;
    float ah = sigm(uu)*sigm(2.f*(uu - SS));
    g_uu[g1] = uu; g_ah[g1] = ah;
    sq1[r][tx] = ah*ah;
    if (!diag) {
      size_t g2 = base + (size_t)(j0+r)*LL + i0 + tx;
      float uv2 = u[g2];
      float uu2v = sigm(2.f*(uv2 - SS))*uv2;
      float ah2v = sigm(uu2v)*sigm(2.f*(uu2v - SS));
      g_uu[g2] = uu2v; g_ah[g2] = ah2v;
      sq2[r][tx] = ah2v*ah2v;
    }
  }
  __syncthreads();

  #pragma unroll
  for (int k=0;k<4;k++){
    int r = ty + 8*k;
    float sT = diag ? sq1[tx][r] : sq2[tx][r];
    float a1 = 0.5f*(sq1[r][tx] + sT) * mcalc(fI, r, fJ, tx);
    float rs1 = wsum(a1);
    if (tx==0) g_partial[(b*LL + i0 + r)*32 + J] = rs1;
    if (!diag){
      float a2 = 0.5f*(sq2[r][tx] + sq1[tx][r]) * mcalc(fJ, r, fI, tx);
      float rs2 = wsum(a2);
      if (tx==0) g_partial[(b*LL + j0 + r)*32 + I] = rs2;
    }
  }
}

// ---------------- per-row: lmbd update + s ----------------
__global__ void row_kernel(const float* __restrict__ lW1, const float* __restrict__ lb1,
                           const float* __restrict__ lW2, const float* __restrict__ lb2,
                           int first)
{
  int i = blockIdx.x*blockDim.x + threadIdx.x;
  if (i >= BB*LL) return;
  float rs = 0.f;
  const float4* pp = (const float4*)(g_partial + (size_t)i*32);
  #pragma unroll
  for (int q=0;q<8;q++){ float4 v = pp[q]; rs += (v.x+v.y) + (v.z+v.w); }
  float lg = fmaxf(rs - 1.f, 0.f);
  float lm;
  if (first) {
    lm = lg;                            // W_PEN = 1
  } else {
    float l0 = g_lmbd[i];
    float h0 = fmaxf(fmaf(lW1[0],l0,fmaf(lW1[1],lg,lb1[0])), 0.f);
    float h1 = fmaxf(fmaf(lW1[2],l0,fmaf(lW1[3],lg,lb1[1])), 0.f);
    float h2 = fmaxf(fmaf(lW1[4],l0,fmaf(lW1[5],lg,lb1[2])), 0.f);
    lm = fmaxf(fmaf(lW2[0],h0,fmaf(lW2[1],h1,fmaf(lW2[2],h2,lb2[0]))), 0.f);
  }
  g_lmbd[i] = lm;
  g_s[i] = lm * sigm(2.f*(rs - 1.f));
}

// ---------------- main per-timestep kernel ----------------
__global__ void __launch_bounds__(256)
step_kernel(const float* __restrict__ x,
  const float* __restrict__ aW1, const float* __restrict__ ab1,
  const float* __restrict__ aW2, const float* __restrict__ ab2,
  const float* __restrict__ rW1, const float* __restrict__ rb1,
  const float* __restrict__ rW2, const float* __restrict__ rb2,
  float* __restrict__ out)   // pre-offset to timestep slice
{
  int b = blockIdx.y;
  int I, J; decode_pair(blockIdx.x, I, J);
  bool diag = (I==J);
  int i0 = I*32, j0 = J*32;
  int tid = threadIdx.x, tx = tid&31, ty = tid>>5;

  __shared__ float uu1[32][33], uu2[32][33];
  __shared__ float sq1[32][33], sq2[32][33];
  __shared__ float fI[4][32], fJ[4][32];
  __shared__ float sI[32], sJ[32];
  __shared__ float wA[16], wR[16];

  if (tid < 32) {
    float4 v = ((const float4*)x)[b*LL + i0 + tid];
    fI[0][tid]=v.x; fI[1][tid]=v.y; fI[2][tid]=v.z; fI[3][tid]=v.w;
    sI[tid] = g_s[b*LL + i0 + tid];
  } else if (tid < 64) {
    int l = tid-32;
    float4 v = ((const float4*)x)[b*LL + j0 + l];
    fJ[0][l]=v.x; fJ[1][l]=v.y; fJ[2][l]=v.z; fJ[3][l]=v.w;
    sJ[l] = g_s[b*LL + j0 + l];
  } else if (tid < 80) {
    int l = tid-64;
    wA[l] = (l<9) ? aW1[l] : (l<12) ? ab1[l-9] : (l<15) ? aW2[l-12] : ab2[0];
  } else if (tid < 96) {
    int l = tid-80;
    wR[l] = (l<9) ? rW1[l] : (l<12) ? rb1[l-9] : (l<15) ? rW2[l-12] : rb2[0];
  }

  float ah1[4], ah2[4];
  const size_t base = (size_t)b*LL*LL;
  #pragma unroll
  for (int k=0;k<4;k++){
    int r = ty + 8*k;
    size_t g1 = base + (size_t)(i0+r)*LL + j0 + tx;
    uu1[r][tx] = g_uu[g1];
    ah1[k]     = g_ah[g1];
    if (!diag) {
      size_t g2 = base + (size_t)(j0+r)*LL + i0 + tx;
      uu2[r][tx] = g_uu[g2];
      ah2[k]     = g_ah[g2];
    }
  }
  __syncthreads();

  float m1[4], m2[4];
  #pragma unroll
  for (int k=0;k<4;k++){
    int r = ty + 8*k;
    // tile1: rows in I, cols in J
    m1[k] = mcalc(fI, r, fJ, tx);
    float u12 = uu1[r][tx];
    float u21 = diag ? uu1[tx][r] : uu2[tx][r];
    float grad = ah1[k]*m1[k]*(-0.5f*(u12+u21) + sI[r] + sJ[tx]);
    float o    = mlp3(wA, ah1[k], grad, u12);
    float rho  = mlp3(wR, ah1[k], grad, u12);
    float ahn  = fminf(fmaxf(o - rho, 0.f), 1.f);
    size_t g1 = base + (size_t)(i0+r)*LL + j0 + tx;
    g_ah[g1] = ahn;
    sq1[r][tx] = ahn*ahn;
    if (!diag) {
      m2[k] = mcalc(fJ, r, fI, tx);
      float v12 = uu2[r][tx];
      float v21 = uu1[tx][r];
      float grad2 = ah2[k]*m2[k]*(-0.5f*(v12+v21) + sJ[r] + sI[tx]);
      float o2   = mlp3(wA, ah2[k], grad2, v12);
      float rho2 = mlp3(wR, ah2[k], grad2, v12);
      float ahn2 = fminf(fmaxf(o2 - rho2, 0.f), 1.f);
      size_t g2 = base + (size_t)(j0+r)*LL + i0 + tx;
      g_ah[g2] = ahn2;
      sq2[r][tx] = ahn2*ahn2;
    }
  }
  __syncthreads();

  #pragma unroll
  for (int k=0;k<4;k++){
    int r = ty + 8*k;
    float sT = diag ? sq1[tx][r] : sq2[tx][r];
    float a1 = 0.5f*(sq1[r][tx] + sT)*m1[k];
    out[base + (size_t)(i0+r)*LL + j0 + tx] = a1;
    float rs1 = wsum(a1);
    if (tx==0) g_partial[(b*LL + i0 + r)*32 + J] = rs1;
    if (!diag){
      float a2 = 0.5f*(sq2[r][tx] + sq1[tx][r])*m2[k];
      out[base + (size_t)(j0+r)*LL + i0 + tx] = a2;
      float rs2 = wsum(a2);
      if (tx==0) g_partial[(b*LL + j0 + r)*32 + I] = rs2;
    }
  }
}

extern "C" void kernel_launch(void* const* d_in, const int* in_sizes, int n_in,
                              void* d_out, int out_size)
{
  // metadata order: u, x, timesteps, aW1, ab1, aW2, ab2, rW1, rb1, rW2, rb2, lW1, lb1, lW2, lb2
  // (hedge in case the scalar `timesteps` isn't materialized as an input)
  int off = (n_in >= 15) ? 3 : 2;
  const float* u   = (const float*)d_in[0];
  const float* x   = (const float*)d_in[1];
  const float* aW1 = (const float*)d_in[off+0];
  const float* ab1 = (const float*)d_in[off+1];
  const float* aW2 = (const float*)d_in[off+2];
  const float* ab2 = (const float*)d_in[off+3];
  const float* rW1 = (const float*)d_in[off+4];
  const float* rb1 = (const float*)d_in[off+5];
  const float* rW2 = (const float*)d_in[off+6];
  const float* rb2 = (const float*)d_in[off+7];
  const float* lW1 = (const float*)d_in[off+8];
  const float* lb1 = (const float*)d_in[off+9];
  const float* lW2 = (const float*)d_in[off+10];
  const float* lb2 = (const float*)d_in[off+11];
  float* out = (float*)d_out;

  dim3 grid(528, BB);   // 32*33/2 tile pairs per batch
  init_kernel<<<grid, 256>>>(u, x);
  for (int t = 0; t < NT; ++t) {
    int tm = (t==0) ? 0 : (t-1);
    row_kernel<<<(BB*LL)/256, 256>>>(lW1 + tm*6, lb1 + tm*3, lW2 + tm*3, lb2 + tm,
                                     (t==0) ? 1 : 0);
    step_kernel<<<grid, 256>>>(x, aW1 + t*9, ab1 + t*3, aW2 + t*3, ab2 + t,
                               rW1 + t*9, rb1 + t*3, rW2 + t*3, rb2 + t,
                               out + (size_t)t*BB*LL*LL);
  }
}